// round 3
// baseline (speedup 1.0000x reference)
#include <cuda_runtime.h>
#include <math.h>

#define NB 4
#define NP 2048
#define ND 768
#define NH 12
#define NHD 64
#define NROWS (NB*NP)        // 8192
#define NPP (NP*NP)          // 4194304 = 2^22

// ---- scratch (static device globals; no dynamic allocation) ----
__device__ float g_h[NROWS*ND];                 // LN output (reused for LN1 and LN2)
__device__ float g_qkv[(long long)NROWS*3*ND];  // fused qkv, layout (b,p,3D)
__device__ float g_S[(long long)NB*NH*NPP];     // attention scores/weights, (b,h,p,q)
__device__ float g_xattn[NROWS*ND];             // attn out + residual
__device__ float g_fc1[(long long)NROWS*4*ND];  // gelu(fc1)

// ============================================================
// LayerNorm: one block per row, 256 threads, D=768 (3 per thread)
// ============================================================
__global__ void ln_kernel(const float* __restrict__ x, const float* __restrict__ gw,
                          const float* __restrict__ gb, float* __restrict__ out) {
    const int row = blockIdx.x;
    const float* xr = x + (long long)row * ND;
    float v[3];
    float s = 0.f, sq = 0.f;
#pragma unroll
    for (int i = 0; i < 3; i++) {
        v[i] = xr[threadIdx.x + i*256];
        s += v[i];
        sq += v[i]*v[i];
    }
#pragma unroll
    for (int o = 16; o > 0; o >>= 1) {
        s  += __shfl_xor_sync(0xffffffffu, s,  o);
        sq += __shfl_xor_sync(0xffffffffu, sq, o);
    }
    __shared__ float sh_s[8], sh_q[8];
    if ((threadIdx.x & 31) == 0) { sh_s[threadIdx.x >> 5] = s; sh_q[threadIdx.x >> 5] = sq; }
    __syncthreads();
    s = 0.f; sq = 0.f;
#pragma unroll
    for (int i = 0; i < 8; i++) { s += sh_s[i]; sq += sh_q[i]; }
    const float mu   = s * (1.f/ND);
    const float var  = sq * (1.f/ND) - mu*mu;
    const float rstd = rsqrtf(var + 1e-5f);
    float* orow = out + (long long)row * ND;
#pragma unroll
    for (int i = 0; i < 3; i++) {
        int c = threadIdx.x + i*256;
        orow[c] = (v[i] - mu) * rstd * gw[c] + gb[c];
    }
}

// ============================================================
// Softmax over the HEADS axis: for each (b,p,q), normalize the 12
// head scores. In-place on g_S. One element of (b,p,q) per thread.
// ============================================================
__global__ void softmax_heads(float* __restrict__ S) {
    const long long idx = (long long)blockIdx.x * 256 + threadIdx.x;  // over NB*NPP
    const int b = (int)(idx >> 22);           // NPP == 2^22
    const long long r = idx & (NPP - 1);
    float* base = S + (long long)b * NH * NPP + r;
    float v[NH];
    float m = -1e30f;
#pragma unroll
    for (int h = 0; h < NH; h++) { v[h] = base[(long long)h * NPP]; m = fmaxf(m, v[h]); }
    float sum = 0.f;
#pragma unroll
    for (int h = 0; h < NH; h++) { v[h] = __expf(v[h] - m); sum += v[h]; }
    const float inv = 1.f / sum;
#pragma unroll
    for (int h = 0; h < NH; h++) base[(long long)h * NPP] = v[h] * inv;
}

// ============================================================
// Generic tiled SGEMM, C = alpha * A@B (+bias)(+gelu)(+residual)
//   A: MxK row-major (lda). B: KxN row-major (ldb), or if TB: B is the
//   NxK matrix whose transpose is used (B[n][k] at B + n*ldb + k).
//   Batched over blockIdx.z with per-(b,h) affine offsets: z -> (zb=z/NH, zh=z%NH),
//   ptr += zb*s?b + zh*s?h.  Residual uses C's strides/ldc.
// EPI: 0 = alpha only; 1 = +bias; 2 = +bias then x*Phi(x) (exact gelu);
//      3 = +bias +residual; 4 = +residual.
// ============================================================
template<int BM,int BN,int BK,int TM,int TN,bool TB,int EPI>
__global__ __launch_bounds__((BM/TM)*(BN/TN))
void gemm_kernel(int M, int N, int K,
    const float* __restrict__ A, int lda, long long sAb, long long sAh,
    const float* __restrict__ B, int ldb, long long sBb, long long sBh,
    float*       __restrict__ C, int ldc, long long sCb, long long sCh,
    const float* __restrict__ bias, const float* __restrict__ Res, float alpha)
{
    constexpr int NT = (BM/TM)*(BN/TN);
    static_assert(BM*(BK/4) == NT, "A loader mapping");
    static_assert((BK*BN) % NT == 0, "B loader mapping");
    static_assert(!TB || BN*(BK/4) == NT, "TB loader mapping");

    __shared__ float As[BK][BM];
    __shared__ float Bs[BK][BN];

    const int tid = threadIdx.x;
    {
        const int zb = blockIdx.z / NH, zh = blockIdx.z % NH;
        A += zb*sAb + zh*sAh;
        B += zb*sBb + zh*sBh;
        C += zb*sCb + zh*sCh;
        if (EPI >= 3) Res += zb*sCb + zh*sCh;
    }
    const int m0 = blockIdx.y * BM;
    const int n0 = blockIdx.x * BN;
    const int tr = tid / (BN/TN);
    const int tc = tid % (BN/TN);
    const int arow = tid / (BK/4);
    const int acol = (tid % (BK/4)) * 4;

    float acc[TM][TN] = {};

    for (int k0 = 0; k0 < K; k0 += BK) {
        // A tile (BM x BK), stored transposed As[k][m]; float4 along K
        float4 av = *(const float4*)(A + (long long)(m0 + arow)*lda + k0 + acol);
        As[acol+0][arow] = av.x; As[acol+1][arow] = av.y;
        As[acol+2][arow] = av.z; As[acol+3][arow] = av.w;
        if (TB) {
            // B is N-major with K contiguous: Bs[k][n] = B[n][k]
            float4 bv = *(const float4*)(B + (long long)(n0 + arow)*ldb + k0 + acol);
            Bs[acol+0][arow] = bv.x; Bs[acol+1][arow] = bv.y;
            Bs[acol+2][arow] = bv.z; Bs[acol+3][arow] = bv.w;
        } else {
#pragma unroll
            for (int e = 0; e < (BK*BN)/NT; e++) {
                int i = tid + e*NT;
                Bs[i/BN][i%BN] = B[(long long)(k0 + i/BN)*ldb + n0 + (i%BN)];
            }
        }
        __syncthreads();
#pragma unroll
        for (int kk = 0; kk < BK; kk++) {
            float rm[TM], rn[TN];
#pragma unroll
            for (int i = 0; i < TM; i++) rm[i] = As[kk][tr*TM + i];
#pragma unroll
            for (int j = 0; j < TN; j++) rn[j] = Bs[kk][tc*TN + j];
#pragma unroll
            for (int i = 0; i < TM; i++)
#pragma unroll
                for (int j = 0; j < TN; j++)
                    acc[i][j] = fmaf(rm[i], rn[j], acc[i][j]);
        }
        __syncthreads();
    }

#pragma unroll
    for (int i = 0; i < TM; i++) {
        const long long m = m0 + tr*TM + i;
#pragma unroll
        for (int j = 0; j < TN; j++) {
            const int n = n0 + tc*TN + j;
            float v = acc[i][j] * alpha;
            if (EPI == 1 || EPI == 2 || EPI == 3) v += bias[n];
            if (EPI == 2) v *= normcdff(v);                 // exact GELU: x * Phi(x)
            if (EPI == 3 || EPI == 4) v += Res[m*ldc + n];
            C[m*ldc + n] = v;
        }
    }
}

// ============================================================
// launch: LN1 -> QKV -> S=QK^T*scale -> softmax(heads) -> O=AV+res
//         -> LN2 -> FC1+gelu -> FC2+bias+res
// ============================================================
extern "C" void kernel_launch(void* const* d_in, const int* in_sizes, int n_in,
                              void* d_out, int out_size) {
    (void)in_sizes; (void)n_in; (void)out_size;
    const float* x    = (const float*)d_in[0];
    const float* ln1w = (const float*)d_in[1];
    const float* ln1b = (const float*)d_in[2];
    const float* wqkv = (const float*)d_in[3];
    const float* bqkv = (const float*)d_in[4];
    const float* ln2w = (const float*)d_in[5];
    const float* ln2b = (const float*)d_in[6];
    const float* wfc1 = (const float*)d_in[7];
    const float* bfc1 = (const float*)d_in[8];
    const float* wfc2 = (const float*)d_in[9];
    const float* bfc2 = (const float*)d_in[10];
    float* out = (float*)d_out;

    float *h, *qkv, *S, *xat, *fc1;
    cudaGetSymbolAddress((void**)&h,   g_h);
    cudaGetSymbolAddress((void**)&qkv, g_qkv);
    cudaGetSymbolAddress((void**)&S,   g_S);
    cudaGetSymbolAddress((void**)&xat, g_xattn);
    cudaGetSymbolAddress((void**)&fc1, g_fc1);

    const float scale = 0.125f;  // 64^-0.5
    const long long sQKVb = (long long)NP * 3 * ND;  // batch stride inside qkv
    const long long sSb   = (long long)NH * NPP;

    // 1) LN1: h = LN(x)
    ln_kernel<<<NROWS, 256>>>(x, ln1w, ln1b, h);

    // 2) qkv = h @ Wqkv + b   (8192 x 2304 x 768)
    gemm_kernel<128,128,8,8,8,false,1><<<dim3(3*ND/128, NROWS/128, 1), 256>>>(
        NROWS, 3*ND, ND,
        h, ND, 0, 0,
        wqkv, 3*ND, 0, 0,
        qkv, 3*ND, 0, 0,
        bqkv, nullptr, 1.f);

    // 3) S[b,h] = Q[b,h] @ K[b,h]^T * scale   (48 x 2048 x 2048 x 64, NT)
    gemm_kernel<128,128,8,8,8,true,0><<<dim3(NP/128, NP/128, NB*NH), 256>>>(
        NP, NP, NHD,
        qkv,      3*ND, sQKVb, NHD,      // Q: offset h*64
        qkv + ND, 3*ND, sQKVb, NHD,      // K: offset D + h*64 (N-major, K contiguous)
        S, NP, sSb, (long long)NPP,
        nullptr, nullptr, scale);

    // 4) softmax over heads (in place)
    softmax_heads<<<(unsigned)((long long)NB*NPP/256), 256>>>(S);

    // 5) xat[b,p,h*64+d] = sum_q A[b,h,p,q] V[b,h,q,d]  + x (residual)
    gemm_kernel<128,64,8,8,4,false,4><<<dim3(1, NP/128, NB*NH), 256>>>(
        NP, NHD, NP,
        S, NP, sSb, (long long)NPP,
        qkv + 2*ND, 3*ND, sQKVb, NHD,    // V
        xat, ND, (long long)NP*ND, NHD,  // write into (b,p,hd) layout
        nullptr, x, 1.f);

    // 6) LN2: h = LN(xat)
    ln_kernel<<<NROWS, 256>>>(xat, ln2w, ln2b, h);

    // 7) fc1 = gelu(h @ Wfc1 + b)   (8192 x 3072 x 768)
    gemm_kernel<128,128,8,8,8,false,2><<<dim3(4*ND/128, NROWS/128, 1), 256>>>(
        NROWS, 4*ND, ND,
        h, ND, 0, 0,
        wfc1, 4*ND, 0, 0,
        fc1, 4*ND, 0, 0,
        bfc1, nullptr, 1.f);

    // 8) out = fc1 @ Wfc2 + b + xat   (8192 x 768 x 3072)
    gemm_kernel<128,128,8,8,8,false,3><<<dim3(ND/128, NROWS/128, 1), 256>>>(
        NROWS, ND, 4*ND,
        fc1, 4*ND, 0, 0,
        wfc2, ND, 0, 0,
        out, ND, 0, 0,
        bfc2, xat, 1.f);
}

// round 4
// speedup vs baseline: 3.2658x; 3.2658x over previous
#include <cuda_runtime.h>
#include <math.h>
#include <stdint.h>

#define NB 4
#define NP 2048
#define ND 768
#define NH 12
#define NHD 64
#define NROWS (NB*NP)        // 8192
#define NPP (NP*NP)          // 4194304 = 2^22

// ---- scratch (static device globals; no dynamic allocation) ----
__device__ float g_h[NROWS*ND];
__device__ float g_qkv[(long long)NROWS*3*ND];
__device__ float g_S[(long long)NB*NH*NPP];
__device__ float g_xattn[NROWS*ND];
__device__ float g_fc1[(long long)NROWS*4*ND];

// ============================================================
// LayerNorm: one block per row, 256 threads, D=768
// ============================================================
__global__ void ln_kernel(const float* __restrict__ x, const float* __restrict__ gw,
                          const float* __restrict__ gb, float* __restrict__ out) {
    const int row = blockIdx.x;
    const float* xr = x + (long long)row * ND;
    float v[3];
    float s = 0.f, sq = 0.f;
#pragma unroll
    for (int i = 0; i < 3; i++) {
        v[i] = xr[threadIdx.x + i*256];
        s += v[i];
        sq += v[i]*v[i];
    }
#pragma unroll
    for (int o = 16; o > 0; o >>= 1) {
        s  += __shfl_xor_sync(0xffffffffu, s,  o);
        sq += __shfl_xor_sync(0xffffffffu, sq, o);
    }
    __shared__ float sh_s[8], sh_q[8];
    if ((threadIdx.x & 31) == 0) { sh_s[threadIdx.x >> 5] = s; sh_q[threadIdx.x >> 5] = sq; }
    __syncthreads();
    s = 0.f; sq = 0.f;
#pragma unroll
    for (int i = 0; i < 8; i++) { s += sh_s[i]; sq += sh_q[i]; }
    const float mu   = s * (1.f/ND);
    const float var  = sq * (1.f/ND) - mu*mu;
    const float rstd = rsqrtf(var + 1e-5f);
    float* orow = out + (long long)row * ND;
#pragma unroll
    for (int i = 0; i < 3; i++) {
        int c = threadIdx.x + i*256;
        orow[c] = (v[i] - mu) * rstd * gw[c] + gb[c];
    }
}

// ============================================================
// Softmax over the HEADS axis (strided 12-way), in-place on S.
// ============================================================
__global__ void softmax_heads(float* __restrict__ S) {
    const long long idx = (long long)blockIdx.x * 256 + threadIdx.x;
    const int b = (int)(idx >> 22);
    const long long r = idx & (NPP - 1);
    float* base = S + (long long)b * NH * NPP + r;
    float v[NH];
    float m = -1e30f;
#pragma unroll
    for (int h = 0; h < NH; h++) { v[h] = base[(long long)h * NPP]; m = fmaxf(m, v[h]); }
    float sum = 0.f;
#pragma unroll
    for (int h = 0; h < NH; h++) { v[h] = __expf(v[h] - m); sum += v[h]; }
    const float inv = 1.f / sum;
#pragma unroll
    for (int h = 0; h < NH; h++) base[(long long)h * NPP] = v[h] * inv;
}

// ============================================================
// TF32 tensor-core helpers
// ============================================================
__device__ __forceinline__ uint32_t f2tf(float x) {
    uint32_t r; asm("cvt.rna.tf32.f32 %0, %1;" : "=r"(r) : "f"(x)); return r;
}
__device__ __forceinline__ void mma8(float* d, const uint32_t* a, const uint32_t* b) {
    asm volatile("mma.sync.aligned.m16n8k8.row.col.f32.tf32.tf32.f32 "
        "{%0,%1,%2,%3}, {%4,%5,%6,%7}, {%8,%9}, {%0,%1,%2,%3};\n"
        : "+f"(d[0]), "+f"(d[1]), "+f"(d[2]), "+f"(d[3])
        : "r"(a[0]), "r"(a[1]), "r"(a[2]), "r"(a[3]), "r"(b[0]), "r"(b[1]));
}
__device__ __forceinline__ void cp16(uint32_t smem_dst, const void* g) {
    asm volatile("cp.async.cg.shared.global [%0], [%1], 16;\n" :: "r"(smem_dst), "l"(g));
}

// ============================================================
// Tensor-core GEMM: C = alpha*A@B (+bias)(+gelu)(+residual)
//   A: MxK row-major. B: KxN row-major, or if TB: NxK row-major
//   (its transpose is multiplied). Batched over blockIdx.z with
//   z -> (zb=z/NH, zh=z%NH) affine offsets.
// EPI: 0=alpha; 1=+bias; 2=+bias,gelu; 3=+bias,+res; 4=+res.
// 8 warps = 256 threads. Warp grid WRM x WRN.
// SMEM: A as [m][k] pad BK+4 (conflict-free frag loads: bank=4g+tig),
//       B as [k][n] pad BN+8 (bank=8tig+g), TB-B as [n][k] pad BK+4.
// ============================================================
template<int BM,int BN,int BK,int WRM,int WRN,bool TB,int EPI>
__global__ __launch_bounds__(256, 2)
void gemm_tc(int M, int N, int K,
    const float* __restrict__ A, int lda, long long sAb, long long sAh,
    const float* __restrict__ B, int ldb, long long sBb, long long sBh,
    float*       __restrict__ C, int ldc, long long sCb, long long sCh,
    const float* __restrict__ bias, const float* __restrict__ Res, float alpha)
{
    constexpr int BKp = BK + 4;
    constexpr int BNp = BN + 8;
    constexpr int ASZ = BM * BKp;
    constexpr int BSZ = TB ? BN * BKp : BK * BNp;
    constexpr int MT  = BM / WRM / 16;   // 16-row mma tiles per warp
    constexpr int NT2 = BN / WRN / 8;    // 8-col mma tiles per warp

    extern __shared__ float sm[];
    const uint32_t smb = (uint32_t)__cvta_generic_to_shared(sm);

    const int tid = threadIdx.x;
    {
        const int zb = blockIdx.z / NH, zh = blockIdx.z % NH;
        A += zb*sAb + zh*sAh;
        B += zb*sBb + zh*sBh;
        C += zb*sCb + zh*sCh;
        if (EPI >= 3) Res += zb*sCb + zh*sCh;
    }
    const int m0 = blockIdx.y * BM;
    const int n0 = blockIdx.x * BN;

    const int lane = tid & 31, wid = tid >> 5;
    const int g = lane >> 2, tg = lane & 3;
    const int wm = (wid / WRN) * (BM / WRM);
    const int wn = (wid % WRN) * (BN / WRN);

    float acc[MT][NT2][4] = {};

    // ---- async tile loaders ----
    auto load_tile = [&](int stg, int k0) {
#pragma unroll
        for (int i = tid; i < BM*(BK/4); i += 256) {
            int m = i / (BK/4), k4 = (i % (BK/4)) * 4;
            cp16(smb + (uint32_t)((stg*(ASZ+BSZ) + m*BKp + k4) * 4),
                 A + (long long)(m0 + m)*lda + k0 + k4);
        }
        if (TB) {
#pragma unroll
            for (int i = tid; i < BN*(BK/4); i += 256) {
                int n = i / (BK/4), k4 = (i % (BK/4)) * 4;
                cp16(smb + (uint32_t)((stg*(ASZ+BSZ) + ASZ + n*BKp + k4) * 4),
                     B + (long long)(n0 + n)*ldb + k0 + k4);
            }
        } else {
#pragma unroll
            for (int i = tid; i < BK*(BN/4); i += 256) {
                int k = i / (BN/4), n4 = (i % (BN/4)) * 4;
                cp16(smb + (uint32_t)((stg*(ASZ+BSZ) + ASZ + k*BNp + n4) * 4),
                     B + (long long)(k0 + k)*ldb + n0 + n4);
            }
        }
    };

    const int T = K / BK;
    load_tile(0, 0);
    asm volatile("cp.async.commit_group;\n" ::: "memory");

    for (int t = 0; t < T; t++) {
        if (t + 1 < T) {
            load_tile((t + 1) & 1, (t + 1) * BK);
            asm volatile("cp.async.commit_group;\n" ::: "memory");
            asm volatile("cp.async.wait_group 1;\n" ::: "memory");
        } else {
            asm volatile("cp.async.wait_group 0;\n" ::: "memory");
        }
        __syncthreads();

        const float* a_s = sm + (t & 1) * (ASZ + BSZ);
        const float* b_s = a_s + ASZ;
#pragma unroll
        for (int kk = 0; kk < BK/8; kk++) {
            uint32_t af[MT][4];
#pragma unroll
            for (int mt = 0; mt < MT; mt++) {
                const float* p = a_s + (wm + mt*16 + g)*BKp + kk*8;
                af[mt][0] = f2tf(p[tg]);
                af[mt][1] = f2tf(p[8*BKp + tg]);
                af[mt][2] = f2tf(p[tg + 4]);
                af[mt][3] = f2tf(p[8*BKp + tg + 4]);
            }
            uint32_t bf[NT2][2];
#pragma unroll
            for (int nt = 0; nt < NT2; nt++) {
                if (TB) {
                    const float* p = b_s + (wn + nt*8 + g)*BKp + kk*8;
                    bf[nt][0] = f2tf(p[tg]);
                    bf[nt][1] = f2tf(p[tg + 4]);
                } else {
                    const float* p = b_s + (kk*8 + tg)*BNp + wn + nt*8 + g;
                    bf[nt][0] = f2tf(p[0]);
                    bf[nt][1] = f2tf(p[4*BNp]);
                }
            }
#pragma unroll
            for (int mt = 0; mt < MT; mt++)
#pragma unroll
                for (int nt = 0; nt < NT2; nt++)
                    mma8(acc[mt][nt], af[mt], bf[nt]);
        }
        __syncthreads();
    }

    // ---- epilogue: c0,c1 at (m, 2tg..2tg+1), c2,c3 at (m+8, ...) ----
#pragma unroll
    for (int mt = 0; mt < MT; mt++) {
#pragma unroll
        for (int nt = 0; nt < NT2; nt++) {
            const int n_ = n0 + wn + nt*8 + 2*tg;
#pragma unroll
            for (int half = 0; half < 2; half++) {
                const long long m_ = m0 + wm + mt*16 + g + half*8;
                float v0 = acc[mt][nt][half*2 + 0] * alpha;
                float v1 = acc[mt][nt][half*2 + 1] * alpha;
                if (EPI == 1 || EPI == 2 || EPI == 3) { v0 += bias[n_]; v1 += bias[n_ + 1]; }
                if (EPI == 2) { v0 *= normcdff(v0); v1 *= normcdff(v1); }
                if (EPI == 3 || EPI == 4) {
                    float2 r = *(const float2*)(Res + m_*ldc + n_);
                    v0 += r.x; v1 += r.y;
                }
                *(float2*)(C + m_*ldc + n_) = make_float2(v0, v1);
            }
        }
    }
}

// ============================================================
extern "C" void kernel_launch(void* const* d_in, const int* in_sizes, int n_in,
                              void* d_out, int out_size) {
    (void)in_sizes; (void)n_in; (void)out_size;
    const float* x    = (const float*)d_in[0];
    const float* ln1w = (const float*)d_in[1];
    const float* ln1b = (const float*)d_in[2];
    const float* wqkv = (const float*)d_in[3];
    const float* bqkv = (const float*)d_in[4];
    const float* ln2w = (const float*)d_in[5];
    const float* ln2b = (const float*)d_in[6];
    const float* wfc1 = (const float*)d_in[7];
    const float* bfc1 = (const float*)d_in[8];
    const float* wfc2 = (const float*)d_in[9];
    const float* bfc2 = (const float*)d_in[10];
    float* out = (float*)d_out;

    float *h, *qkv, *S, *xat, *fc1;
    cudaGetSymbolAddress((void**)&h,   g_h);
    cudaGetSymbolAddress((void**)&qkv, g_qkv);
    cudaGetSymbolAddress((void**)&S,   g_S);
    cudaGetSymbolAddress((void**)&xat, g_xattn);
    cudaGetSymbolAddress((void**)&fc1, g_fc1);

    const float scale = 0.125f;
    const long long sQKVb = (long long)NP * 3 * ND;
    const long long sSb   = (long long)NH * NPP;

    // dynamic smem sizes (double-buffered)
    const int smem_std = 2 * (128*36 + 32*136) * 4;  // 71680
    const int smem_tb  = 2 * (128*36 + 128*36) * 4;  // 73728
    const int smem_av  = 2 * (128*36 + 32*72)  * 4;  // 55296

    auto* kQKV = gemm_tc<128,128,32,2,4,false,1>;
    auto* kQK  = gemm_tc<128,128,32,2,4,true, 0>;
    auto* kAV  = gemm_tc<128, 64,32,4,2,false,4>;
    auto* kFC1 = gemm_tc<128,128,32,2,4,false,2>;
    auto* kFC2 = gemm_tc<128,128,32,2,4,false,3>;
    cudaFuncSetAttribute(kQKV, cudaFuncAttributeMaxDynamicSharedMemorySize, smem_std);
    cudaFuncSetAttribute(kQK,  cudaFuncAttributeMaxDynamicSharedMemorySize, smem_tb);
    cudaFuncSetAttribute(kAV,  cudaFuncAttributeMaxDynamicSharedMemorySize, smem_av);
    cudaFuncSetAttribute(kFC1, cudaFuncAttributeMaxDynamicSharedMemorySize, smem_std);
    cudaFuncSetAttribute(kFC2, cudaFuncAttributeMaxDynamicSharedMemorySize, smem_std);

    // 1) LN1
    ln_kernel<<<NROWS, 256>>>(x, ln1w, ln1b, h);

    // 2) qkv = h @ Wqkv + b   (8192 x 2304 x 768)
    kQKV<<<dim3(3*ND/128, NROWS/128, 1), 256, smem_std>>>(
        NROWS, 3*ND, ND,
        h, ND, 0, 0,
        wqkv, 3*ND, 0, 0,
        qkv, 3*ND, 0, 0,
        bqkv, nullptr, 1.f);

    // 3) S = Q @ K^T * scale   (48x: 2048 x 2048 x 64)
    kQK<<<dim3(NP/128, NP/128, NB*NH), 256, smem_tb>>>(
        NP, NP, NHD,
        qkv,      3*ND, sQKVb, NHD,
        qkv + ND, 3*ND, sQKVb, NHD,
        S, NP, sSb, (long long)NPP,
        nullptr, nullptr, scale);

    // 4) softmax over heads
    softmax_heads<<<(unsigned)((long long)NB*NPP/256), 256>>>(S);

    // 5) xat = A @ V + x   (48x: 2048 x 64 x 2048)
    kAV<<<dim3(1, NP/128, NB*NH), 256, smem_av>>>(
        NP, NHD, NP,
        S, NP, sSb, (long long)NPP,
        qkv + 2*ND, 3*ND, sQKVb, NHD,
        xat, ND, (long long)NP*ND, NHD,
        nullptr, x, 1.f);

    // 6) LN2
    ln_kernel<<<NROWS, 256>>>(xat, ln2w, ln2b, h);

    // 7) fc1 = gelu(h @ Wfc1 + b)   (8192 x 3072 x 768)
    kFC1<<<dim3(4*ND/128, NROWS/128, 1), 256, smem_std>>>(
        NROWS, 4*ND, ND,
        h, ND, 0, 0,
        wfc1, 4*ND, 0, 0,
        fc1, 4*ND, 0, 0,
        bfc1, nullptr, 1.f);

    // 8) out = fc1 @ Wfc2 + b + xat   (8192 x 768 x 3072)
    kFC2<<<dim3(ND/128, NROWS/128, 1), 256, smem_std>>>(
        NROWS, ND, 4*ND,
        fc1, 4*ND, 0, 0,
        wfc2, ND, 0, 0,
        out, ND, 0, 0,
        bfc2, xat, 1.f);
}

// round 6
// speedup vs baseline: 5.5158x; 1.6889x over previous
#include <cuda_runtime.h>
#include <cuda_fp16.h>
#include <math.h>
#include <stdint.h>

#define NB 4
#define NP 2048
#define ND 768
#define NH 12
#define NHD 64
#define NROWS (NB*NP)        // 8192
#define NPP (NP*NP)          // 2^22

// ---- scratch (static device globals) ----
__device__ __half g_h[NROWS*ND];                    // LN output (fp16)
__device__ __half g_qkv[(long long)NROWS*3*ND];     // fused qkv (fp16)
__device__ __half g_S[(long long)NB*NH*NPP];        // attention scores (fp16)
__device__ float  g_xattn[NROWS*ND];                // attn out + residual (fp32)
__device__ __half g_fc1[(long long)NROWS*4*ND];     // gelu(fc1) (fp16)
__device__ __half g_wt[2304*768 + 3072*768 + 768*3072];  // transposed fp16 weights

#define WT_QKV 0
#define WT_FC1 (2304*768)
#define WT_FC2 (2304*768 + 3072*768)

// ============================================================
// helpers
// ============================================================
__device__ __forceinline__ void cp16(uint32_t smem_dst, const void* g) {
    asm volatile("cp.async.cg.shared.global [%0], [%1], 16;\n" :: "r"(smem_dst), "l"(g));
}
__device__ __forceinline__ void mma16(float* d, const uint32_t* a, const uint32_t* b) {
    asm volatile("mma.sync.aligned.m16n8k16.row.col.f32.f16.f16.f32 "
        "{%0,%1,%2,%3}, {%4,%5,%6,%7}, {%8,%9}, {%0,%1,%2,%3};\n"
        : "+f"(d[0]), "+f"(d[1]), "+f"(d[2]), "+f"(d[3])
        : "r"(a[0]), "r"(a[1]), "r"(a[2]), "r"(a[3]), "r"(b[0]), "r"(b[1]));
}
__device__ __forceinline__ void st2o(__half* p, float a, float b) { *(__half2*)p = __floats2half2_rn(a, b); }
__device__ __forceinline__ void st2o(float* p, float a, float b) { *(float2*)p = make_float2(a, b); }

// ============================================================
// LayerNorm -> fp16 output
// ============================================================
__global__ void ln_kernel(const float* __restrict__ x, const float* __restrict__ gw,
                          const float* __restrict__ gb, __half* __restrict__ out) {
    const int row = blockIdx.x;
    const float* xr = x + (long long)row * ND;
    float v[3];
    float s = 0.f, sq = 0.f;
#pragma unroll
    for (int i = 0; i < 3; i++) {
        v[i] = xr[threadIdx.x + i*256];
        s += v[i]; sq += v[i]*v[i];
    }
#pragma unroll
    for (int o = 16; o > 0; o >>= 1) {
        s  += __shfl_xor_sync(0xffffffffu, s,  o);
        sq += __shfl_xor_sync(0xffffffffu, sq, o);
    }
    __shared__ float sh_s[8], sh_q[8];
    if ((threadIdx.x & 31) == 0) { sh_s[threadIdx.x >> 5] = s; sh_q[threadIdx.x >> 5] = sq; }
    __syncthreads();
    s = 0.f; sq = 0.f;
#pragma unroll
    for (int i = 0; i < 8; i++) { s += sh_s[i]; sq += sh_q[i]; }
    const float mu   = s * (1.f/ND);
    const float var  = sq * (1.f/ND) - mu*mu;
    const float rstd = rsqrtf(var + 1e-5f);
    __half* orow = out + (long long)row * ND;
#pragma unroll
    for (int i = 0; i < 3; i++) {
        int c = threadIdx.x + i*256;
        orow[c] = __float2half((v[i] - mu) * rstd * gw[c] + gb[c]);
    }
}

// ============================================================
// Weight transpose + fp16: Wt[n][k] = half(W[k][n])
// ============================================================
__global__ void transpose_h(const float* __restrict__ W, __half* __restrict__ Wt, int K, int N) {
    __shared__ float t[32][33];
    const int k0 = blockIdx.x * 32, n0 = blockIdx.y * 32;
    const int tx = threadIdx.x & 31, ty = threadIdx.x >> 5;
#pragma unroll
    for (int i = ty; i < 32; i += 8) t[i][tx] = W[(long long)(k0 + i) * N + n0 + tx];
    __syncthreads();
#pragma unroll
    for (int i = ty; i < 32; i += 8) Wt[(long long)(n0 + i) * K + k0 + tx] = __float2half(t[tx][i]);
}

// ============================================================
// Softmax over HEADS axis, fp16 S, 2 q-positions per thread
// ============================================================
__global__ void softmax_heads_h(__half* __restrict__ S) {
    const long long idx = (long long)blockIdx.x * 256 + threadIdx.x;   // over NB*NPP/2
    const int b = (int)(idx >> 21);
    const long long r = (idx & ((1LL << 21) - 1)) << 1;
    __half2* base = (__half2*)(S + (long long)b * NH * NPP + r);
    float2 v[NH];
    float mx = -1e30f, my = -1e30f;
#pragma unroll
    for (int h = 0; h < NH; h++) {
        v[h] = __half22float2(base[(long long)h * (NPP/2)]);
        mx = fmaxf(mx, v[h].x); my = fmaxf(my, v[h].y);
    }
    float sx = 0.f, sy = 0.f;
#pragma unroll
    for (int h = 0; h < NH; h++) {
        v[h].x = __expf(v[h].x - mx); v[h].y = __expf(v[h].y - my);
        sx += v[h].x; sy += v[h].y;
    }
    const float ix = 1.f / sx, iy = 1.f / sy;
#pragma unroll
    for (int h = 0; h < NH; h++)
        base[(long long)h * (NPP/2)] = __floats2half2_rn(v[h].x * ix, v[h].y * iy);
}

// ============================================================
// fp16 mma.sync GEMM: C = alpha*A@B' (+bias)(+gelu)(+residual)
//   A: MxK fp16 row-major (k-contiguous).
//   BL=0: B is Bt[n][k] fp16 (k-contiguous)  -> C = A @ Bt^T
//   BL=1: B is  B[k][n] fp16 (n-contiguous)  -> C = A @ B
// Batched over blockIdx.z: z -> (zb=z/NH, zh=z%NH) affine offsets.
// EPI: 0=alpha; 1=+bias; 2=+bias,gelu; 3=+bias,+res; 4=+res.
// 8 warps, warp grid WRM x WRN. Smem pads give conflict-free frags.
// ============================================================
template<int BM,int BN,int BK,int WRM,int WRN,int BL,int EPI,class TC>
__global__ __launch_bounds__(256, 2)
void gemm_h(int M, int N, int K,
    const __half* __restrict__ A, int lda, long long sAb, long long sAh,
    const __half* __restrict__ B, int ldb, long long sBb, long long sBh,
    TC*           __restrict__ C, int ldc, long long sCb, long long sCh,
    const float* __restrict__ bias, const float* __restrict__ Res, float alpha)
{
    constexpr int BKp = BK + 8;
    constexpr int BNp = BN + 8;
    constexpr int ACH = BK / 8;                    // 16B chunks per A row
    constexpr int ASZ = BM * BKp * 2;              // bytes
    constexpr int BSZ = (BL == 0) ? BN * BKp * 2 : BK * BNp * 2;
    constexpr int MT  = BM / WRM / 16;
    constexpr int NT  = BN / WRN / 8;

    extern __shared__ char smc[];
    const uint32_t smb = (uint32_t)__cvta_generic_to_shared(smc);

    const int tid = threadIdx.x;
    {
        const int zb = blockIdx.z / NH, zh = blockIdx.z % NH;
        A += zb*sAb + zh*sAh;
        B += zb*sBb + zh*sBh;
        C += zb*sCb + zh*sCh;
        if (EPI >= 3) Res += zb*sCb + zh*sCh;
    }
    const int m0 = blockIdx.y * BM;
    const int n0 = blockIdx.x * BN;

    const int lane = tid & 31, wid = tid >> 5;
    const int g = lane >> 2, tg = lane & 3;
    const int wm = (wid / WRN) * (BM / WRM);
    const int wn = (wid % WRN) * (BN / WRN);

    float acc[MT][NT][4] = {};

    auto load_tile = [&](int stg, int k0) {
        const uint32_t base = smb + (uint32_t)(stg * (ASZ + BSZ));
#pragma unroll
        for (int i = tid; i < BM*ACH; i += 256) {
            int m = i / ACH, c = i % ACH;
            cp16(base + (uint32_t)((m*BKp + c*8) * 2),
                 A + (long long)(m0 + m)*lda + k0 + c*8);
        }
        const uint32_t bb = base + (uint32_t)ASZ;
        if (BL == 0) {
#pragma unroll
            for (int i = tid; i < BN*ACH; i += 256) {
                int n = i / ACH, c = i % ACH;
                cp16(bb + (uint32_t)((n*BKp + c*8) * 2),
                     B + (long long)(n0 + n)*ldb + k0 + c*8);
            }
        } else {
#pragma unroll
            for (int i = tid; i < BK*(BN/8); i += 256) {
                int k = i / (BN/8), c = i % (BN/8);
                cp16(bb + (uint32_t)((k*BNp + c*8) * 2),
                     B + (long long)(k0 + k)*ldb + n0 + c*8);
            }
        }
        asm volatile("cp.async.commit_group;\n" ::: "memory");
    };

    const int T = K / BK;
    load_tile(0, 0);

    for (int t = 0; t < T; t++) {
        if (t + 1 < T) {
            load_tile((t + 1) & 1, (t + 1) * BK);
            asm volatile("cp.async.wait_group 1;\n" ::: "memory");
        } else {
            asm volatile("cp.async.wait_group 0;\n" ::: "memory");
        }
        __syncthreads();

        const char* stgp = smc + (t & 1) * (ASZ + BSZ);
        const __half* a_s = (const __half*)stgp;
        const __half* b_s = (const __half*)(stgp + ASZ);
#pragma unroll
        for (int kk = 0; kk < BK/16; kk++) {
            uint32_t af[MT][4];
#pragma unroll
            for (int mt = 0; mt < MT; mt++) {
                const __half* p = a_s + (wm + mt*16 + g)*BKp + kk*16;
                af[mt][0] = *(const uint32_t*)(p + 2*tg);
                af[mt][1] = *(const uint32_t*)(p + 8*BKp + 2*tg);
                af[mt][2] = *(const uint32_t*)(p + 2*tg + 8);
                af[mt][3] = *(const uint32_t*)(p + 8*BKp + 2*tg + 8);
            }
            uint32_t bf[NT][2];
#pragma unroll
            for (int nt = 0; nt < NT; nt++) {
                if (BL == 0) {
                    const __half* q = b_s + (wn + nt*8 + g)*BKp + kk*16;
                    bf[nt][0] = *(const uint32_t*)(q + 2*tg);
                    bf[nt][1] = *(const uint32_t*)(q + 2*tg + 8);
                } else {
                    const __half* q = b_s + (kk*16 + 2*tg)*BNp + wn + nt*8 + g;
                    uint32_t l0 = *(const uint16_t*)(q);
                    uint32_t h0 = *(const uint16_t*)(q + BNp);
                    uint32_t l1 = *(const uint16_t*)(q + 8*BNp);
                    uint32_t h1 = *(const uint16_t*)(q + 9*BNp);
                    bf[nt][0] = l0 | (h0 << 16);
                    bf[nt][1] = l1 | (h1 << 16);
                }
            }
#pragma unroll
            for (int mt = 0; mt < MT; mt++)
#pragma unroll
                for (int nt = 0; nt < NT; nt++)
                    mma16(acc[mt][nt], af[mt], bf[nt]);
        }
        __syncthreads();
    }

    // ---- epilogue ----
#pragma unroll
    for (int mt = 0; mt < MT; mt++) {
#pragma unroll
        for (int nt = 0; nt < NT; nt++) {
            const int n_ = n0 + wn + nt*8 + 2*tg;
#pragma unroll
            for (int half = 0; half < 2; half++) {
                const long long m_ = m0 + wm + mt*16 + g + half*8;
                float v0 = acc[mt][nt][half*2 + 0] * alpha;
                float v1 = acc[mt][nt][half*2 + 1] * alpha;
                if (EPI == 1 || EPI == 2 || EPI == 3) { v0 += bias[n_]; v1 += bias[n_ + 1]; }
                if (EPI == 2) { v0 *= normcdff(v0); v1 *= normcdff(v1); }
                if (EPI == 3 || EPI == 4) {
                    float2 r = *(const float2*)(Res + m_*ldc + n_);
                    v0 += r.x; v1 += r.y;
                }
                st2o(C + m_*ldc + n_, v0, v1);
            }
        }
    }
}

// ============================================================
extern "C" void kernel_launch(void* const* d_in, const int* in_sizes, int n_in,
                              void* d_out, int out_size) {
    (void)in_sizes; (void)n_in; (void)out_size;
    const float* x    = (const float*)d_in[0];
    const float* ln1w = (const float*)d_in[1];
    const float* ln1b = (const float*)d_in[2];
    const float* wqkv = (const float*)d_in[3];
    const float* bqkv = (const float*)d_in[4];
    const float* ln2w = (const float*)d_in[5];
    const float* ln2b = (const float*)d_in[6];
    const float* wfc1 = (const float*)d_in[7];
    const float* bfc1 = (const float*)d_in[8];
    const float* wfc2 = (const float*)d_in[9];
    const float* bfc2 = (const float*)d_in[10];
    float* out = (float*)d_out;

    __half *h, *qkv, *S, *fc1, *wt;
    float *xat;
    cudaGetSymbolAddress((void**)&h,   g_h);
    cudaGetSymbolAddress((void**)&qkv, g_qkv);
    cudaGetSymbolAddress((void**)&S,   g_S);
    cudaGetSymbolAddress((void**)&xat, g_xattn);
    cudaGetSymbolAddress((void**)&fc1, g_fc1);
    cudaGetSymbolAddress((void**)&wt,  g_wt);

    const float scale = 0.125f;
    const long long sQKVb = (long long)NP * 3 * ND;
    const long long sSb   = (long long)NH * NPP;

    // kernels + smem sizes (double-buffered)
    auto* kQKV = gemm_h<128,128,64,2,4,0,1,__half>;   // h @ WqkvT + b -> fp16
    auto* kQK  = gemm_h<128,128,64,2,4,0,0,__half>;   // Q @ K^T * scale -> fp16
    auto* kAV  = gemm_h<128, 64,64,2,4,1,4,float >;   // S @ V + x -> fp32
    auto* kFC1 = gemm_h<128,128,64,2,4,0,2,__half>;   // gelu(h @ Wfc1T + b) -> fp16
    auto* kFC2 = gemm_h<128,128,64,2,4,0,3,float >;   // fc1 @ Wfc2T + b + xat -> fp32
    const int sm128 = 2 * (128*72*2 + 128*72*2);      // 73728
    const int smAV  = 2 * (128*72*2 + 64*72*2);       // 55296
    cudaFuncSetAttribute(kQKV, cudaFuncAttributeMaxDynamicSharedMemorySize, sm128);
    cudaFuncSetAttribute(kQK,  cudaFuncAttributeMaxDynamicSharedMemorySize, sm128);
    cudaFuncSetAttribute(kAV,  cudaFuncAttributeMaxDynamicSharedMemorySize, smAV);
    cudaFuncSetAttribute(kFC1, cudaFuncAttributeMaxDynamicSharedMemorySize, sm128);
    cudaFuncSetAttribute(kFC2, cudaFuncAttributeMaxDynamicSharedMemorySize, sm128);

    // 0) transpose + fp16 weights
    transpose_h<<<dim3(ND/32, 3*ND/32), 256>>>(wqkv, wt + WT_QKV, ND, 3*ND);
    transpose_h<<<dim3(ND/32, 4*ND/32), 256>>>(wfc1, wt + WT_FC1, ND, 4*ND);
    transpose_h<<<dim3(4*ND/32, ND/32), 256>>>(wfc2, wt + WT_FC2, 4*ND, ND);

    // 1) LN1
    ln_kernel<<<NROWS, 256>>>(x, ln1w, ln1b, h);

    // 2) qkv = h @ Wqkv + b   (8192 x 2304 x 768)
    kQKV<<<dim3(3*ND/128, NROWS/128, 1), 256, sm128>>>(
        NROWS, 3*ND, ND,
        h, ND, 0, 0,
        wt + WT_QKV, ND, 0, 0,
        qkv, 3*ND, 0, 0,
        bqkv, nullptr, 1.f);

    // 3) S = Q @ K^T * scale -> fp16  (48x: 2048 x 2048 x 64)
    kQK<<<dim3(NP/128, NP/128, NB*NH), 256, sm128>>>(
        NP, NP, NHD,
        qkv,      3*ND, sQKVb, NHD,
        qkv + ND, 3*ND, sQKVb, NHD,
        S, NP, sSb, (long long)NPP,
        nullptr, nullptr, scale);

    // 4) softmax over heads (fp16, in place)
    softmax_heads_h<<<(unsigned)((long long)NB*NPP/2/256), 256>>>(S);

    // 5) xat = S @ V + x   (48x: 2048 x 64 x 2048)
    kAV<<<dim3(1, NP/128, NB*NH), 256, smAV>>>(
        NP, NHD, NP,
        S, NP, sSb, (long long)NPP,
        qkv + 2*ND, 3*ND, sQKVb, NHD,
        xat, ND, (long long)NP*ND, NHD,
        nullptr, x, 1.f);

    // 6) LN2
    ln_kernel<<<NROWS, 256>>>(xat, ln2w, ln2b, h);

    // 7) fc1 = gelu(h @ Wfc1 + b)   (8192 x 3072 x 768)
    kFC1<<<dim3(4*ND/128, NROWS/128, 1), 256, sm128>>>(
        NROWS, 4*ND, ND,
        h, ND, 0, 0,
        wt + WT_FC1, ND, 0, 0,
        fc1, 4*ND, 0, 0,
        bfc1, nullptr, 1.f);

    // 8) out = fc1 @ Wfc2 + b + xat   (8192 x 768 x 3072)
    kFC2<<<dim3(ND/128, NROWS/128, 1), 256, sm128>>>(
        NROWS, ND, 4*ND,
        fc1, 4*ND, 0, 0,
        wt + WT_FC2, 4*ND, 0, 0,
        out, ND, 0, 0,
        bfc2, xat, 1.f);
}

// round 7
// speedup vs baseline: 5.6065x; 1.0165x over previous
#include <cuda_runtime.h>
#include <cuda_fp16.h>
#include <math.h>
#include <stdint.h>

#define NB 4
#define NP 2048
#define ND 768
#define NH 12
#define NHD 64
#define NROWS (NB*NP)        // 8192
#define NPP (NP*NP)          // 2^22

// ---- scratch (static device globals) ----
__device__ __half g_h[NROWS*ND];
__device__ __half g_qkv[(long long)NROWS*3*ND];
__device__ __half g_S[(long long)NB*NH*NPP];        // normalized attention A (fp16)
__device__ float  g_xattn[NROWS*ND];
__device__ __half g_fc1[(long long)NROWS*4*ND];
__device__ __half g_wt[2304*768 + 3072*768 + 768*3072];

#define WT_QKV 0
#define WT_FC1 (2304*768)
#define WT_FC2 (2304*768 + 3072*768)

// ============================================================
// helpers
// ============================================================
__device__ __forceinline__ void cp16(uint32_t smem_dst, const void* g) {
    asm volatile("cp.async.cg.shared.global [%0], [%1], 16;\n" :: "r"(smem_dst), "l"(g));
}
__device__ __forceinline__ void mma16(float* d, const uint32_t* a, const uint32_t* b) {
    asm volatile("mma.sync.aligned.m16n8k16.row.col.f32.f16.f16.f32 "
        "{%0,%1,%2,%3}, {%4,%5,%6,%7}, {%8,%9}, {%0,%1,%2,%3};\n"
        : "+f"(d[0]), "+f"(d[1]), "+f"(d[2]), "+f"(d[3])
        : "r"(a[0]), "r"(a[1]), "r"(a[2]), "r"(a[3]), "r"(b[0]), "r"(b[1]));
}
__device__ __forceinline__ void st2o(__half* p, float a, float b) { *(__half2*)p = __floats2half2_rn(a, b); }
__device__ __forceinline__ void st2o(float* p, float a, float b) { *(float2*)p = make_float2(a, b); }

// ============================================================
// LayerNorm -> fp16 output
// ============================================================
__global__ void ln_kernel(const float* __restrict__ x, const float* __restrict__ gw,
                          const float* __restrict__ gb, __half* __restrict__ out) {
    const int row = blockIdx.x;
    const float* xr = x + (long long)row * ND;
    float v[3];
    float s = 0.f, sq = 0.f;
#pragma unroll
    for (int i = 0; i < 3; i++) {
        v[i] = xr[threadIdx.x + i*256];
        s += v[i]; sq += v[i]*v[i];
    }
#pragma unroll
    for (int o = 16; o > 0; o >>= 1) {
        s  += __shfl_xor_sync(0xffffffffu, s,  o);
        sq += __shfl_xor_sync(0xffffffffu, sq, o);
    }
    __shared__ float sh_s[8], sh_q[8];
    if ((threadIdx.x & 31) == 0) { sh_s[threadIdx.x >> 5] = s; sh_q[threadIdx.x >> 5] = sq; }
    __syncthreads();
    s = 0.f; sq = 0.f;
#pragma unroll
    for (int i = 0; i < 8; i++) { s += sh_s[i]; sq += sh_q[i]; }
    const float mu   = s * (1.f/ND);
    const float var  = sq * (1.f/ND) - mu*mu;
    const float rstd = rsqrtf(var + 1e-5f);
    __half* orow = out + (long long)row * ND;
#pragma unroll
    for (int i = 0; i < 3; i++) {
        int c = threadIdx.x + i*256;
        orow[c] = __float2half((v[i] - mu) * rstd * gw[c] + gb[c]);
    }
}

// ============================================================
// Weight transpose + fp16
// ============================================================
__global__ void transpose_h(const float* __restrict__ W, __half* __restrict__ Wt, int K, int N) {
    __shared__ float t[32][33];
    const int k0 = blockIdx.x * 32, n0 = blockIdx.y * 32;
    const int tx = threadIdx.x & 31, ty = threadIdx.x >> 5;
#pragma unroll
    for (int i = ty; i < 32; i += 8) t[i][tx] = W[(long long)(k0 + i) * N + n0 + tx];
    __syncthreads();
#pragma unroll
    for (int i = ty; i < 32; i += 8) Wt[(long long)(n0 + i) * K + k0 + tx] = __float2half(t[tx][i]);
}

// ============================================================
// FUSED: S = softmax_heads(Q K^T * scale) -> A (fp16, (b,h,p,q))
// CTA = (q-tile 64, p-tile 64, batch). Loops 12 heads with
// double-buffered cp.async Q/K tiles; parks per-head scores in
// SMEM (fp16, pad-72); then 12-way softmax + direct global write.
// SMEM: [0, 36864) two stages of (Q 64x72 + K 64x72) fp16
//       [36864, 147456) scores 12 x 64 x 72 fp16
// ============================================================
#define QKSM 147456

__global__ __launch_bounds__(256, 1)
void qk_softmax(const __half* __restrict__ qkv, __half* __restrict__ A) {
    extern __shared__ char smc[];
    const uint32_t smb = (uint32_t)__cvta_generic_to_shared(smc);
    const int tid = threadIdx.x, lane = tid & 31, wid = tid >> 5;
    const int Q0 = blockIdx.x * 64, P0 = blockIdx.y * 64, b = blockIdx.z;
    const __half* qb = qkv + (long long)b * NP * 3 * ND;

    auto load = [&](int h) {
        const uint32_t base = smb + (uint32_t)((h & 1) * 18432);
#pragma unroll
        for (int e = 0; e < 2; e++) {
            int i = tid + e * 256;
            int r = i >> 3, c = i & 7;
            cp16(base + (uint32_t)((r*72 + c*8) * 2),
                 qb + (long long)(P0 + r) * 2304 + h*64 + c*8);
        }
#pragma unroll
        for (int e = 0; e < 2; e++) {
            int i = tid + e * 256;
            int r = i >> 3, c = i & 7;
            cp16(base + 9216u + (uint32_t)((r*72 + c*8) * 2),
                 qb + ND + (long long)(Q0 + r) * 2304 + h*64 + c*8);
        }
        asm volatile("cp.async.commit_group;\n" ::: "memory");
    };

    const int g = lane >> 2, tg = lane & 3;
    const int wm = (wid >> 2) * 32, wn = (wid & 3) * 16;   // warp grid 2x4, tile 32p x 16q
    __half* Ssm = (__half*)(smc + 36864);

    load(0);
#pragma unroll
    for (int h = 0; h < NH; h++) {
        if (h < NH - 1) {
            load(h + 1);
            asm volatile("cp.async.wait_group 1;\n" ::: "memory");
        } else {
            asm volatile("cp.async.wait_group 0;\n" ::: "memory");
        }
        __syncthreads();
        const __half* qs = (const __half*)(smc + (h & 1) * 18432);
        const __half* ks = qs + 4608;

        float acc[2][2][4] = {};
#pragma unroll
        for (int kk = 0; kk < 4; kk++) {
            uint32_t af[2][4], bf[2][2];
#pragma unroll
            for (int mt = 0; mt < 2; mt++) {
                const __half* p_ = qs + (wm + mt*16 + g)*72 + kk*16;
                af[mt][0] = *(const uint32_t*)(p_ + 2*tg);
                af[mt][1] = *(const uint32_t*)(p_ + 8*72 + 2*tg);
                af[mt][2] = *(const uint32_t*)(p_ + 2*tg + 8);
                af[mt][3] = *(const uint32_t*)(p_ + 8*72 + 2*tg + 8);
            }
#pragma unroll
            for (int nt = 0; nt < 2; nt++) {
                const __half* q_ = ks + (wn + nt*8 + g)*72 + kk*16;
                bf[nt][0] = *(const uint32_t*)(q_ + 2*tg);
                bf[nt][1] = *(const uint32_t*)(q_ + 2*tg + 8);
            }
#pragma unroll
            for (int mt = 0; mt < 2; mt++)
#pragma unroll
                for (int nt = 0; nt < 2; nt++)
                    mma16(acc[mt][nt], af[mt], bf[nt]);
        }
        // park scaled scores (fp16) in SMEM
        __half* sh = Ssm + h * 4608;
#pragma unroll
        for (int mt = 0; mt < 2; mt++)
#pragma unroll
            for (int nt = 0; nt < 2; nt++) {
                const int qc = wn + nt*8 + 2*tg;
#pragma unroll
                for (int hf = 0; hf < 2; hf++) {
                    const int pr = wm + mt*16 + g + hf*8;
                    *(__half2*)(sh + pr*72 + qc) =
                        __floats2half2_rn(acc[mt][nt][hf*2] * 0.125f,
                                          acc[mt][nt][hf*2+1] * 0.125f);
                }
            }
        __syncthreads();
    }

    // ---- softmax over heads + write normalized A ----
    __half* Ab = A + (long long)b * NH * NPP;
#pragma unroll
    for (int r = 0; r < 8; r++) {
        const int pr = wid * 8 + r;
        float2 v[NH];
        float mx = -1e30f, my = -1e30f;
#pragma unroll
        for (int h = 0; h < NH; h++) {
            v[h] = __half22float2(*(const __half2*)(Ssm + h*4608 + pr*72 + 2*lane));
            mx = fmaxf(mx, v[h].x); my = fmaxf(my, v[h].y);
        }
        float sx = 0.f, sy = 0.f;
#pragma unroll
        for (int h = 0; h < NH; h++) {
            v[h].x = __expf(v[h].x - mx); v[h].y = __expf(v[h].y - my);
            sx += v[h].x; sy += v[h].y;
        }
        const float ix = 1.f / sx, iy = 1.f / sy;
        const long long rowoff = (long long)(P0 + pr) * NP + Q0 + 2*lane;
#pragma unroll
        for (int h = 0; h < NH; h++)
            *(__half2*)(Ab + (long long)h * NPP + rowoff) =
                __floats2half2_rn(v[h].x * ix, v[h].y * iy);
    }
}

// ============================================================
// fp16 mma.sync GEMM (QKV / AV / FC1 / FC2)
// ============================================================
template<int BM,int BN,int BK,int WRM,int WRN,int BL,int EPI,class TC>
__global__ __launch_bounds__(256, 2)
void gemm_h(int M, int N, int K,
    const __half* __restrict__ A, int lda, long long sAb, long long sAh,
    const __half* __restrict__ B, int ldb, long long sBb, long long sBh,
    TC*           __restrict__ C, int ldc, long long sCb, long long sCh,
    const float* __restrict__ bias, const float* __restrict__ Res, float alpha)
{
    constexpr int BKp = BK + 8;
    constexpr int BNp = BN + 8;
    constexpr int ACH = BK / 8;
    constexpr int ASZ = BM * BKp * 2;
    constexpr int BSZ = (BL == 0) ? BN * BKp * 2 : BK * BNp * 2;
    constexpr int MT  = BM / WRM / 16;
    constexpr int NT  = BN / WRN / 8;

    extern __shared__ char smc[];
    const uint32_t smb = (uint32_t)__cvta_generic_to_shared(smc);

    const int tid = threadIdx.x;
    {
        const int zb = blockIdx.z / NH, zh = blockIdx.z % NH;
        A += zb*sAb + zh*sAh;
        B += zb*sBb + zh*sBh;
        C += zb*sCb + zh*sCh;
        if (EPI >= 3) Res += zb*sCb + zh*sCh;
    }
    const int m0 = blockIdx.y * BM;
    const int n0 = blockIdx.x * BN;

    const int lane = tid & 31, wid = tid >> 5;
    const int g = lane >> 2, tg = lane & 3;
    const int wm = (wid / WRN) * (BM / WRM);
    const int wn = (wid % WRN) * (BN / WRN);

    float acc[MT][NT][4] = {};

    auto load_tile = [&](int stg, int k0) {
        const uint32_t base = smb + (uint32_t)(stg * (ASZ + BSZ));
#pragma unroll
        for (int i = tid; i < BM*ACH; i += 256) {
            int m = i / ACH, c = i % ACH;
            cp16(base + (uint32_t)((m*BKp + c*8) * 2),
                 A + (long long)(m0 + m)*lda + k0 + c*8);
        }
        const uint32_t bb = base + (uint32_t)ASZ;
        if (BL == 0) {
#pragma unroll
            for (int i = tid; i < BN*ACH; i += 256) {
                int n = i / ACH, c = i % ACH;
                cp16(bb + (uint32_t)((n*BKp + c*8) * 2),
                     B + (long long)(n0 + n)*ldb + k0 + c*8);
            }
        } else {
#pragma unroll
            for (int i = tid; i < BK*(BN/8); i += 256) {
                int k = i / (BN/8), c = i % (BN/8);
                cp16(bb + (uint32_t)((k*BNp + c*8) * 2),
                     B + (long long)(k0 + k)*ldb + n0 + c*8);
            }
        }
        asm volatile("cp.async.commit_group;\n" ::: "memory");
    };

    const int T = K / BK;
    load_tile(0, 0);

    for (int t = 0; t < T; t++) {
        if (t + 1 < T) {
            load_tile((t + 1) & 1, (t + 1) * BK);
            asm volatile("cp.async.wait_group 1;\n" ::: "memory");
        } else {
            asm volatile("cp.async.wait_group 0;\n" ::: "memory");
        }
        __syncthreads();

        const char* stgp = smc + (t & 1) * (ASZ + BSZ);
        const __half* a_s = (const __half*)stgp;
        const __half* b_s = (const __half*)(stgp + ASZ);
#pragma unroll
        for (int kk = 0; kk < BK/16; kk++) {
            uint32_t af[MT][4];
#pragma unroll
            for (int mt = 0; mt < MT; mt++) {
                const __half* p = a_s + (wm + mt*16 + g)*BKp + kk*16;
                af[mt][0] = *(const uint32_t*)(p + 2*tg);
                af[mt][1] = *(const uint32_t*)(p + 8*BKp + 2*tg);
                af[mt][2] = *(const uint32_t*)(p + 2*tg + 8);
                af[mt][3] = *(const uint32_t*)(p + 8*BKp + 2*tg + 8);
            }
            uint32_t bf[NT][2];
#pragma unroll
            for (int nt = 0; nt < NT; nt++) {
                if (BL == 0) {
                    const __half* q = b_s + (wn + nt*8 + g)*BKp + kk*16;
                    bf[nt][0] = *(const uint32_t*)(q + 2*tg);
                    bf[nt][1] = *(const uint32_t*)(q + 2*tg + 8);
                } else {
                    const __half* q = b_s + (kk*16 + 2*tg)*BNp + wn + nt*8 + g;
                    uint32_t l0 = *(const uint16_t*)(q);
                    uint32_t h0 = *(const uint16_t*)(q + BNp);
                    uint32_t l1 = *(const uint16_t*)(q + 8*BNp);
                    uint32_t h1 = *(const uint16_t*)(q + 9*BNp);
                    bf[nt][0] = l0 | (h0 << 16);
                    bf[nt][1] = l1 | (h1 << 16);
                }
            }
#pragma unroll
            for (int mt = 0; mt < MT; mt++)
#pragma unroll
                for (int nt = 0; nt < NT; nt++)
                    mma16(acc[mt][nt], af[mt], bf[nt]);
        }
        __syncthreads();
    }

#pragma unroll
    for (int mt = 0; mt < MT; mt++) {
#pragma unroll
        for (int nt = 0; nt < NT; nt++) {
            const int n_ = n0 + wn + nt*8 + 2*tg;
#pragma unroll
            for (int half = 0; half < 2; half++) {
                const long long m_ = m0 + wm + mt*16 + g + half*8;
                float v0 = acc[mt][nt][half*2 + 0] * alpha;
                float v1 = acc[mt][nt][half*2 + 1] * alpha;
                if (EPI == 1 || EPI == 2 || EPI == 3) { v0 += bias[n_]; v1 += bias[n_ + 1]; }
                if (EPI == 2) { v0 *= normcdff(v0); v1 *= normcdff(v1); }
                if (EPI == 3 || EPI == 4) {
                    float2 r = *(const float2*)(Res + m_*ldc + n_);
                    v0 += r.x; v1 += r.y;
                }
                st2o(C + m_*ldc + n_, v0, v1);
            }
        }
    }
}

// ============================================================
extern "C" void kernel_launch(void* const* d_in, const int* in_sizes, int n_in,
                              void* d_out, int out_size) {
    (void)in_sizes; (void)n_in; (void)out_size;
    const float* x    = (const float*)d_in[0];
    const float* ln1w = (const float*)d_in[1];
    const float* ln1b = (const float*)d_in[2];
    const float* wqkv = (const float*)d_in[3];
    const float* bqkv = (const float*)d_in[4];
    const float* ln2w = (const float*)d_in[5];
    const float* ln2b = (const float*)d_in[6];
    const float* wfc1 = (const float*)d_in[7];
    const float* bfc1 = (const float*)d_in[8];
    const float* wfc2 = (const float*)d_in[9];
    const float* bfc2 = (const float*)d_in[10];
    float* out = (float*)d_out;

    __half *h, *qkv, *S, *fc1, *wt;
    float *xat;
    cudaGetSymbolAddress((void**)&h,   g_h);
    cudaGetSymbolAddress((void**)&qkv, g_qkv);
    cudaGetSymbolAddress((void**)&S,   g_S);
    cudaGetSymbolAddress((void**)&xat, g_xattn);
    cudaGetSymbolAddress((void**)&fc1, g_fc1);
    cudaGetSymbolAddress((void**)&wt,  g_wt);

    const long long sQKVb = (long long)NP * 3 * ND;
    const long long sSb   = (long long)NH * NPP;

    auto* kQKV = gemm_h<128,128,64,2,4,0,1,__half>;
    auto* kAV  = gemm_h<128, 64,64,2,4,1,4,float >;
    auto* kFC1 = gemm_h<128,128,64,2,4,0,2,__half>;
    auto* kFC2 = gemm_h<128,128,64,2,4,0,3,float >;
    const int sm128 = 2 * (128*72*2 + 128*72*2);
    const int smAV  = 2 * (128*72*2 + 64*72*2);
    cudaFuncSetAttribute(kQKV, cudaFuncAttributeMaxDynamicSharedMemorySize, sm128);
    cudaFuncSetAttribute(kAV,  cudaFuncAttributeMaxDynamicSharedMemorySize, smAV);
    cudaFuncSetAttribute(kFC1, cudaFuncAttributeMaxDynamicSharedMemorySize, sm128);
    cudaFuncSetAttribute(kFC2, cudaFuncAttributeMaxDynamicSharedMemorySize, sm128);
    cudaFuncSetAttribute(qk_softmax, cudaFuncAttributeMaxDynamicSharedMemorySize, QKSM);

    // 0) transpose + fp16 weights
    transpose_h<<<dim3(ND/32, 3*ND/32), 256>>>(wqkv, wt + WT_QKV, ND, 3*ND);
    transpose_h<<<dim3(ND/32, 4*ND/32), 256>>>(wfc1, wt + WT_FC1, ND, 4*ND);
    transpose_h<<<dim3(4*ND/32, ND/32), 256>>>(wfc2, wt + WT_FC2, 4*ND, ND);

    // 1) LN1
    ln_kernel<<<NROWS, 256>>>(x, ln1w, ln1b, h);

    // 2) qkv = h @ Wqkv + b
    kQKV<<<dim3(3*ND/128, NROWS/128, 1), 256, sm128>>>(
        NROWS, 3*ND, ND,
        h, ND, 0, 0,
        wt + WT_QKV, ND, 0, 0,
        qkv, 3*ND, 0, 0,
        bqkv, nullptr, 1.f);

    // 3+4) fused: A = softmax_heads(Q K^T * scale)
    qk_softmax<<<dim3(NP/64, NP/64, NB), 256, QKSM>>>(qkv, S);

    // 5) xat = A @ V + x
    kAV<<<dim3(1, NP/128, NB*NH), 256, smAV>>>(
        NP, NHD, NP,
        S, NP, sSb, (long long)NPP,
        qkv + 2*ND, 3*ND, sQKVb, NHD,
        xat, ND, (long long)NP*ND, NHD,
        nullptr, x, 1.f);

    // 6) LN2
    ln_kernel<<<NROWS, 256>>>(xat, ln2w, ln2b, h);

    // 7) fc1 = gelu(h @ Wfc1 + b)
    kFC1<<<dim3(4*ND/128, NROWS/128, 1), 256, sm128>>>(
        NROWS, 4*ND, ND,
        h, ND, 0, 0,
        wt + WT_FC1, ND, 0, 0,
        fc1, 4*ND, 0, 0,
        bfc1, nullptr, 1.f);

    // 8) out = fc1 @ Wfc2 + b + xat
    kFC2<<<dim3(ND/128, NROWS/128, 1), 256, sm128>>>(
        NROWS, ND, 4*ND,
        fc1, 4*ND, 0, 0,
        wt + WT_FC2, 4*ND, 0, 0,
        out, ND, 0, 0,
        bfc2, xat, 1.f);
}